// round 3
// baseline (speedup 1.0000x reference)
#include <cuda_runtime.h>
#include <math.h>

#define NB 32      // batch
#define NT 400     // timesteps
#define NU 400     // LSTM units
#define NKG 10     // attention gaussians
#define NC 73      // alphabet
#define NUC 50     // char positions
#define NO 121     // MDN outputs (6*20+1)
#define H4 1600    // 4*NU

// ---------------- packed weights (gate-interleaved float4 per (u,k)) ----------------
__device__ float4 d_P0  [NU*476];  // layer1: [x(3), w(73), h1(400)]
__device__ float4 d_P1r [NU*403];  // layer2 recurrent part: [x(3), h2@Wh1(400)]
__device__ float4 d_P1h [NU*400];  // layer2 h1 part of Wx1
__device__ float4 d_P1w [NU*73];   // layer2 w  part of Wx1
__device__ float4 d_P2r [NU*403];  // layer3 recurrent part: [x(3), h3@Wh2(400)]
__device__ float4 d_P2wh[NU*473];  // layer3 [w(73), h2(400)] part of Wx2

// ---------------- state, transposed [u][b] ----------------
__device__ float d_h1a[NU*NB];
__device__ float d_h1b[NU*NB];
__device__ float d_c1 [NU*NB];
__device__ float d_h2 [NU*NB];
__device__ float d_c2 [NU*NB];
__device__ float d_h3 [NU*NB];
__device__ float d_c3 [NU*NB];
__device__ float d_Z2p[NU*4*NB];
__device__ float d_Z2h[NU*4*NB];
__device__ float d_R3p[NU*4*NB];
__device__ float d_kappa[NB*NKG];
__device__ float d_wT[NC*NB];
__device__ float d_h3all[NT*NU*NB];   // [t][u][b] for MDN head

// ---------------- grid barrier state ----------------
__device__ unsigned d_count;
__device__ volatile unsigned d_release;

// =====================================================================
// pack kernel: gate-interleave all weight matrices + reset barrier state
// =====================================================================
__global__ void pack_kernel(const float* __restrict__ Wx0, const float* __restrict__ Wh0,
                            const float* __restrict__ Wx1, const float* __restrict__ Wh1,
                            const float* __restrict__ Wx2, const float* __restrict__ Wh2)
{
    int idx = blockIdx.x * blockDim.x + threadIdx.x;
    int str = gridDim.x * blockDim.x;
    if (idx == 0) { d_count = 0; d_release = 0; }

    for (int e = idx; e < NU*476; e += str) {
        int u = e / 476, k = e - u*476;
        const float* s = (k < 76) ? (Wx0 + k*H4) : (Wh0 + (k-76)*H4);
        d_P0[e] = make_float4(s[u], s[NU+u], s[2*NU+u], s[3*NU+u]);
    }
    for (int e = idx; e < NU*403; e += str) {
        int u = e / 403, k = e - u*403;
        const float* s = (k < 3) ? (Wx1 + k*H4) : (Wh1 + (k-3)*H4);
        d_P1r[e] = make_float4(s[u], s[NU+u], s[2*NU+u], s[3*NU+u]);
    }
    for (int e = idx; e < NU*400; e += str) {
        int u = e / 400, k = e - u*400;
        const float* s = Wx1 + (76+k)*H4;
        d_P1h[e] = make_float4(s[u], s[NU+u], s[2*NU+u], s[3*NU+u]);
    }
    for (int e = idx; e < NU*73; e += str) {
        int u = e / 73, k = e - u*73;
        const float* s = Wx1 + (3+k)*H4;
        d_P1w[e] = make_float4(s[u], s[NU+u], s[2*NU+u], s[3*NU+u]);
    }
    for (int e = idx; e < NU*403; e += str) {
        int u = e / 403, k = e - u*403;
        const float* s = (k < 3) ? (Wx2 + k*H4) : (Wh2 + (k-3)*H4);
        d_P2r[e] = make_float4(s[u], s[NU+u], s[2*NU+u], s[3*NU+u]);
    }
    for (int e = idx; e < NU*473; e += str) {
        int u = e / 473, k = e - u*473;
        const float* s = Wx2 + (3+k)*H4;
        d_P2wh[e] = make_float4(s[u], s[NU+u], s[2*NU+u], s[3*NU+u]);
    }
}

// =====================================================================
// helpers
// =====================================================================
__device__ __forceinline__ float sigf(float x) { return 1.f / (1.f + expf(-x)); }

__device__ __forceinline__ void gsync(unsigned r, unsigned ncta)
{
    __syncthreads();
    if (threadIdx.x == 0) {
        __threadfence();
        unsigned a = atomicAdd(&d_count, 1u) + 1u;
        if (a == r * ncta) {
            d_release = r;
            __threadfence();
        } else {
            while (d_release < r) { }
        }
        __threadfence();
    }
    __syncthreads();
}

// accumulate 4 gates over a K-segment: per k one broadcast float4 weight load,
// one coalesced per-lane state load (v is [k][b] transposed).
__device__ __forceinline__ void acc_seg(float4& a, const float4* __restrict__ P,
                                        const float* __restrict__ v, int K, int b)
{
#pragma unroll 4
    for (int k = 0; k < K; k++) {
        float hv = __ldg(v + k*NB + b);
        float4 w = __ldg(P + k);
        a.x = fmaf(w.x, hv, a.x);
        a.y = fmaf(w.y, hv, a.y);
        a.z = fmaf(w.z, hv, a.z);
        a.w = fmaf(w.w, hv, a.w);
    }
}

__device__ __forceinline__ void acc_x(float4& a, const float4* __restrict__ P,
                                      float x0, float x1, float x2)
{
    float4 w0 = __ldg(P + 0), w1 = __ldg(P + 1), w2 = __ldg(P + 2);
    a.x = fmaf(w0.x, x0, fmaf(w1.x, x1, fmaf(w2.x, x2, a.x)));
    a.y = fmaf(w0.y, x0, fmaf(w1.y, x1, fmaf(w2.y, x2, a.y)));
    a.z = fmaf(w0.z, x0, fmaf(w1.z, x1, fmaf(w2.z, x2, a.z)));
    a.w = fmaf(w0.w, x0, fmaf(w1.w, x1, fmaf(w2.w, x2, a.w)));
}

// =====================================================================
// persistent RNN kernel
// =====================================================================
__global__ void __launch_bounds__(256, 1)
rnn_kernel(const float* __restrict__ strokes,   // [B][T][3]
           const int*   __restrict__ chars,     // [B][50]
           const int*   __restrict__ lens,      // [B]
           const float* __restrict__ b0, const float* __restrict__ p0,
           const float* __restrict__ b1, const float* __restrict__ p1,
           const float* __restrict__ b2, const float* __restrict__ p2,
           const float* __restrict__ Watt, const float* __restrict__ batt,
           const float* __restrict__ Wmdn, const float* __restrict__ bmdn,
           float* __restrict__ out,             // [B][T][121]
           int ncta)
{
    const int tid  = threadIdx.x;
    const int lane = tid & 31;
    const int wib  = tid >> 5;
    const int gw   = blockIdx.x * 8 + wib;     // global warp id
    const int NW   = ncta * 8;
    unsigned rnd = 0;

    __shared__ float s_w[8][76];               // attention scatter scratch per warp

    // ---- init: zero state ----
    {
        int g = blockIdx.x * 256 + tid, gs = ncta * 256;
        for (int i = g; i < NU*NB; i += gs) {
            d_h1a[i] = 0.f; d_c1[i] = 0.f; d_h2[i] = 0.f; d_c2[i] = 0.f;
            d_h3[i] = 0.f;  d_c3[i] = 0.f;
        }
        for (int i = g; i < NC*NB; i += gs) d_wT[i] = 0.f;
        for (int i = g; i < NB*NKG; i += gs) d_kappa[i] = 0.f;
    }
    gsync(++rnd, (unsigned)ncta);

    const int b = lane;   // lane <-> batch in all GEMV tasks

    for (int t = 0; t < NT; t++) {
        const float* h1prev = (t & 1) ? d_h1b : d_h1a;
        float*       h1cur  = (t & 1) ? d_h1a : d_h1b;

        // per-lane stroke input for this step
        const float* xp = strokes + (b*NT + t)*3;
        float x0 = __ldg(xp + 0), x1 = __ldg(xp + 1), x2 = __ldg(xp + 2);

        // ================= stage 1: z1+LSTM1, R2 (->Z2p), R3 (->R3p) =================
        for (int task = gw; task < 3*NU; task += NW) {
            if (task < NU) {
                int u = task;
                const float4* P = d_P0 + u*476;
                float4 a = make_float4(__ldg(b0+u), __ldg(b0+NU+u), __ldg(b0+2*NU+u), __ldg(b0+3*NU+u));
                acc_x(a, P, x0, x1, x2);
                acc_seg(a, P + 3,  d_wT,   NC, b);
                acc_seg(a, P + 76, h1prev, NU, b);
                int o = u*NB + b;
                float c  = d_c1[o];
                float ig = sigf(a.x + __ldg(p0 + u)      * c);
                float fg = sigf(a.y + __ldg(p0 + NU + u) * c);
                float cn = fg*c + ig*tanhf(a.z);
                float og = sigf(a.w + __ldg(p0 + 2*NU + u) * cn);
                d_c1[o]  = cn;
                h1cur[o] = og * tanhf(cn);
            } else if (task < 2*NU) {
                int u = task - NU;
                const float4* P = d_P1r + u*403;
                float4 a = make_float4(__ldg(b1+u), __ldg(b1+NU+u), __ldg(b1+2*NU+u), __ldg(b1+3*NU+u));
                acc_x(a, P, x0, x1, x2);
                acc_seg(a, P + 3, d_h2, NU, b);
                int o = u*4*NB + b;
                d_Z2p[o] = a.x; d_Z2p[o+NB] = a.y; d_Z2p[o+2*NB] = a.z; d_Z2p[o+3*NB] = a.w;
            } else {
                int u = task - 2*NU;
                const float4* P = d_P2r + u*403;
                float4 a = make_float4(__ldg(b2+u), __ldg(b2+NU+u), __ldg(b2+2*NU+u), __ldg(b2+3*NU+u));
                acc_x(a, P, x0, x1, x2);
                acc_seg(a, P + 3, d_h3, NU, b);
                int o = u*4*NB + b;
                d_R3p[o] = a.x; d_R3p[o+NB] = a.y; d_R3p[o+2*NB] = a.z; d_R3p[o+3*NB] = a.w;
            }
        }
        gsync(++rnd, (unsigned)ncta);

        // ================= stage 2: Z2h = h1@Wx1_h  ||  attention window =================
        for (int task = gw; task < NU + NB; task += NW) {
            if (task < NU) {
                int u = task;
                float4 a = make_float4(0.f, 0.f, 0.f, 0.f);
                acc_seg(a, d_P1h + u*400, h1cur, NU, b);
                int o = u*4*NB + b;
                d_Z2h[o] = a.x; d_Z2h[o+NB] = a.y; d_Z2h[o+2*NB] = a.z; d_Z2h[o+3*NB] = a.w;
            } else {
                int ab = task - NU;             // batch for this attention warp
                float att = 0.f;
                if (lane < 30) {
                    float acc = __ldg(batt + lane);
#pragma unroll 4
                    for (int k = 0; k < NU; k++)
                        acc = fmaf(__ldg(h1cur + k*NB + ab), __ldg(Watt + k*30 + lane), acc);
                    att = acc;
                }
                const unsigned FULL = 0xffffffffu;
                float ah = __shfl_sync(FULL, att, (lane < 10) ? lane      : 0);
                float bh = __shfl_sync(FULL, att, (lane < 10) ? lane + 10 : 10);
                float kh = __shfl_sync(FULL, att, (lane < 10) ? lane + 20 : 20);
                float alpha = 0.f, beta = 0.f, kap = 0.f;
                if (lane < 10) {
                    alpha = expf(ah);
                    beta  = expf(bh);
                    kap   = d_kappa[ab*NKG + lane] + expf(kh);
                    d_kappa[ab*NKG + lane] = kap;
                }
                for (int c = lane; c < NC; c += 32) s_w[wib][c] = 0.f;
                __syncwarp();
                int lb = __ldg(lens + ab);
#pragma unroll
                for (int half = 0; half < 2; half++) {
                    int uu = lane + half*32;
                    float phi = 0.f;
#pragma unroll
                    for (int g = 0; g < NKG; g++) {
                        float ag = __shfl_sync(FULL, alpha, g);
                        float bg = __shfl_sync(FULL, beta,  g);
                        float kg = __shfl_sync(FULL, kap,   g);
                        float df = kg - (float)uu;
                        phi = fmaf(ag, expf(-bg*df*df), phi);
                    }
                    if (uu < NUC && uu < lb) {
                        int c = __ldg(chars + ab*NUC + uu);
                        atomicAdd(&s_w[wib][c], phi);
                    }
                }
                __syncwarp();
                for (int c = lane; c < NC; c += 32) d_wT[c*NB + ab] = s_w[wib][c];
            }
        }
        gsync(++rnd, (unsigned)ncta);

        // ================= stage 3: z2 = Z2p + Z2h + w@Wx1_w -> LSTM2 =================
        for (int task = gw; task < NU; task += NW) {
            int u = task;
            int o4 = u*4*NB + b;
            float4 a = make_float4(d_Z2p[o4]      + d_Z2h[o4],
                                   d_Z2p[o4+NB]   + d_Z2h[o4+NB],
                                   d_Z2p[o4+2*NB] + d_Z2h[o4+2*NB],
                                   d_Z2p[o4+3*NB] + d_Z2h[o4+3*NB]);
            acc_seg(a, d_P1w + u*73, d_wT, NC, b);
            int o = u*NB + b;
            float c  = d_c2[o];
            float ig = sigf(a.x + __ldg(p1 + u)      * c);
            float fg = sigf(a.y + __ldg(p1 + NU + u) * c);
            float cn = fg*c + ig*tanhf(a.z);
            float og = sigf(a.w + __ldg(p1 + 2*NU + u) * cn);
            d_c2[o] = cn;
            d_h2[o] = og * tanhf(cn);
        }
        gsync(++rnd, (unsigned)ncta);

        // ================= stage 4: z3 = R3p + [w,h2]@Wx2 -> LSTM3, store h3 =================
        for (int task = gw; task < NU; task += NW) {
            int u = task;
            int o4 = u*4*NB + b;
            float4 a = make_float4(d_R3p[o4], d_R3p[o4+NB], d_R3p[o4+2*NB], d_R3p[o4+3*NB]);
            const float4* P = d_P2wh + u*473;
            acc_seg(a, P,      d_wT, NC, b);
            acc_seg(a, P + 73, d_h2, NU, b);
            int o = u*NB + b;
            float c  = d_c3[o];
            float ig = sigf(a.x + __ldg(p2 + u)      * c);
            float fg = sigf(a.y + __ldg(p2 + NU + u) * c);
            float cn = fg*c + ig*tanhf(a.z);
            float og = sigf(a.w + __ldg(p2 + 2*NU + u) * cn);
            float hv = og * tanhf(cn);
            d_c3[o] = cn;
            d_h3[o] = hv;
            d_h3all[(t*NU + u)*NB + b] = hv;
        }
        gsync(++rnd, (unsigned)ncta);
    }

    // ================= MDN head: y = h3@Wmdn + bmdn, then transforms =================
    for (int task = gw; task < NB*NT; task += NW) {
        int bb = task / NT;
        int tt = task - bb*NT;
        const float* h3p = d_h3all + (tt*NU)*NB + bb;

        int j0 = lane, j1 = lane + 32, j2 = lane + 64, j3 = lane + 96;
        float a0 = __ldg(bmdn + j0);
        float a1 = __ldg(bmdn + j1);
        float a2 = __ldg(bmdn + j2);
        float a3 = (j3 < NO) ? __ldg(bmdn + j3) : 0.f;
#pragma unroll 4
        for (int k = 0; k < NU; k++) {
            float hv = __ldg(h3p + k*NB);
            const float* wr = Wmdn + k*NO;
            a0 = fmaf(hv, __ldg(wr + j0), a0);
            a1 = fmaf(hv, __ldg(wr + j1), a1);
            a2 = fmaf(hv, __ldg(wr + j2), a2);
            a3 = fmaf(hv, (j3 < NO) ? __ldg(wr + j3) : 0.f, a3);
        }
        // softmax over pi = lanes 0..19 of a0
        const unsigned FULL = 0xffffffffu;
        float v = (lane < 20) ? a0 : -INFINITY;
#pragma unroll
        for (int off = 16; off > 0; off >>= 1) v = fmaxf(v, __shfl_xor_sync(FULL, v, off));
        float e = (lane < 20) ? expf(a0 - v) : 0.f;
        float s = e;
#pragma unroll
        for (int off = 16; off > 0; off >>= 1) s += __shfl_xor_sync(FULL, s, off);

        float* op = out + (bb*NT + tt)*NO;
        // output transform map per column j:
        //   j <  20 : softmax(pi)
        //   20..59  : raw (mu1, mu2)
        //   60..99  : exp (s1, s2)
        //   100..119: tanh (rho)
        //   120     : sigmoid (eos)
        op[j0] = (lane < 20) ? (e / s) : a0;           // 0..31: pi | mu1
        op[j1] = (j1 >= 60) ? expf(a1) : a1;           // 32..63: mu1/mu2 | s1(60-63) FIX
        op[j2] = expf(a2);                             // 64..95: s1 | s2
        if (j3 < NO) {
            float o3;
            if (j3 < 100)      o3 = expf(a3);          // s2
            else if (j3 < 120) o3 = tanhf(a3);         // rho
            else               o3 = sigf(a3);          // eos
            op[j3] = o3;
        }
    }
}

// =====================================================================
// launch
// =====================================================================
extern "C" void kernel_launch(void* const* d_in, const int* in_sizes, int n_in,
                              void* d_out, int out_size)
{
    const float* strokes = (const float*)d_in[0];
    const int*   chars   = (const int*)  d_in[1];
    const int*   lens    = (const int*)  d_in[2];
    const float* Wx0 = (const float*)d_in[3];
    const float* Wh0 = (const float*)d_in[4];
    const float* b0  = (const float*)d_in[5];
    const float* p0  = (const float*)d_in[6];
    const float* Wx1 = (const float*)d_in[7];
    const float* Wh1 = (const float*)d_in[8];
    const float* b1  = (const float*)d_in[9];
    const float* p1  = (const float*)d_in[10];
    const float* Wx2 = (const float*)d_in[11];
    const float* Wh2 = (const float*)d_in[12];
    const float* b2  = (const float*)d_in[13];
    const float* p2  = (const float*)d_in[14];
    const float* Watt = (const float*)d_in[15];
    const float* batt = (const float*)d_in[16];
    const float* Wmdn = (const float*)d_in[17];
    const float* bmdn = (const float*)d_in[18];
    float* out = (float*)d_out;

    int dev = 0;
    cudaGetDevice(&dev);
    int sm = 148;
    cudaDeviceGetAttribute(&sm, cudaDevAttrMultiProcessorCount, dev);
    int ncta = (sm < 150) ? sm : 150;   // 150*8 warps = 1200 = stage-1 task count

    pack_kernel<<<256, 256>>>(Wx0, Wh0, Wx1, Wh1, Wx2, Wh2);
    rnn_kernel<<<ncta, 256>>>(strokes, chars, lens,
                              b0, p0, b1, p1, b2, p2,
                              Watt, batt, Wmdn, bmdn, out, ncta);
}

// round 5
// speedup vs baseline: 2.0110x; 2.0110x over previous
#include <cuda_runtime.h>
#include <math.h>

#define NB 32      // batch
#define NT 400     // timesteps
#define NU 400     // LSTM units
#define NKG 10     // attention gaussians
#define NC 73      // alphabet
#define NUC 50     // char positions
#define NO 121     // MDN outputs
#define H4 1600    // 4*NU
#define NCTA 150
#define NWARPS (NCTA*8)

// ---------------- packed weights (gate-interleaved float4 per (u,k)) ----------------
__device__ float4 d_P0  [NU*476];  // layer1: [x(3), w(73), h1(400)]
__device__ float4 d_P1r [NU*403];  // layer2 recurrent: [x(3), h2@Wh1(400)]
__device__ float4 d_P1h [NU*400];  // layer2 h1 part of Wx1
__device__ float4 d_P1w [NU*73];   // layer2 w part of Wx1
__device__ float4 d_P2r [NU*403];  // layer3 recurrent: [x(3), h3@Wh2(400)]
__device__ float4 d_P2wh[NU*473];  // layer3 [w(73), h2(400)] part of Wx2

// ---------------- state, transposed [u][b] ----------------
__device__ float d_h1a[NU*NB];
__device__ float d_h1b[NU*NB];
__device__ float d_c1 [NU*NB];
__device__ float d_h2 [NU*NB];
__device__ float d_c2 [NU*NB];
__device__ float d_h3 [NU*NB];
__device__ float d_c3 [NU*NB];
__device__ float d_Z2p [NU*4*NB];
__device__ float d_Z2h2[2*NU*4*NB];   // two K-halves of h1@Wx1_h
__device__ float d_R3p [NU*4*NB];
__device__ float d_kappa[NB*NKG];
__device__ float d_wT[NC*NB];
__device__ float d_h3all[NT*NU*NB];

__device__ unsigned d_count;
__device__ unsigned d_release;

// =====================================================================
// pack kernel
// =====================================================================
__global__ void pack_kernel(const float* __restrict__ Wx0, const float* __restrict__ Wh0,
                            const float* __restrict__ Wx1, const float* __restrict__ Wh1,
                            const float* __restrict__ Wx2, const float* __restrict__ Wh2)
{
    int idx = blockIdx.x * blockDim.x + threadIdx.x;
    int str = gridDim.x * blockDim.x;
    if (idx == 0) { d_count = 0; d_release = 0; }

    for (int e = idx; e < NU*476; e += str) {
        int u = e / 476, k = e - u*476;
        const float* s = (k < 76) ? (Wx0 + k*H4) : (Wh0 + (k-76)*H4);
        d_P0[e] = make_float4(s[u], s[NU+u], s[2*NU+u], s[3*NU+u]);
    }
    for (int e = idx; e < NU*403; e += str) {
        int u = e / 403, k = e - u*403;
        const float* s = (k < 3) ? (Wx1 + k*H4) : (Wh1 + (k-3)*H4);
        d_P1r[e] = make_float4(s[u], s[NU+u], s[2*NU+u], s[3*NU+u]);
    }
    for (int e = idx; e < NU*400; e += str) {
        int u = e / 400, k = e - u*400;
        const float* s = Wx1 + (76+k)*H4;
        d_P1h[e] = make_float4(s[u], s[NU+u], s[2*NU+u], s[3*NU+u]);
    }
    for (int e = idx; e < NU*73; e += str) {
        int u = e / 73, k = e - u*73;
        const float* s = Wx1 + (3+k)*H4;
        d_P1w[e] = make_float4(s[u], s[NU+u], s[2*NU+u], s[3*NU+u]);
    }
    for (int e = idx; e < NU*403; e += str) {
        int u = e / 403, k = e - u*403;
        const float* s = (k < 3) ? (Wx2 + k*H4) : (Wh2 + (k-3)*H4);
        d_P2r[e] = make_float4(s[u], s[NU+u], s[2*NU+u], s[3*NU+u]);
    }
    for (int e = idx; e < NU*473; e += str) {
        int u = e / 473, k = e - u*473;
        const float* s = Wx2 + (3+k)*H4;
        d_P2wh[e] = make_float4(s[u], s[NU+u], s[2*NU+u], s[3*NU+u]);
    }
}

// =====================================================================
// helpers
// =====================================================================
__device__ __forceinline__ float sigf(float x) { return 1.f / (1.f + expf(-x)); }

__device__ __forceinline__ unsigned long long pk2(float v) {
    unsigned long long r; asm("mov.b64 %0, {%1, %1};" : "=l"(r) : "f"(v)); return r;
}
__device__ __forceinline__ unsigned long long pk(float lo, float hi) {
    unsigned long long r; asm("mov.b64 %0, {%1, %2};" : "=l"(r) : "f"(lo), "f"(hi)); return r;
}
__device__ __forceinline__ void upk(unsigned long long v, float& lo, float& hi) {
    asm("mov.b64 {%0, %1}, %2;" : "=f"(lo), "=f"(hi) : "l"(v));
}
__device__ __forceinline__ void fma2(unsigned long long& d, unsigned long long a, unsigned long long b) {
    asm("fma.rn.f32x2 %0, %1, %2, %0;" : "+l"(d) : "l"(a), "l"(b));
}

// grid barrier with PROPER acquire/release ordering via scoped strong atomics.
// No fence instruction => no CCTL.IVALL => L1-resident weights survive.
//   arrival: atom.acq_rel.gpu   (release: drains this CTA's prior stores;
//                                acquire: last arriver sees all others' releases)
//   flag:    st.release.gpu    (orders into observers)
//   spin:    ld.acquire.gpu    (synchronizes-with the flag store)
__device__ __forceinline__ void gsync(unsigned r)
{
    __syncthreads();
    if (threadIdx.x == 0) {
        unsigned old;
        asm volatile("{ .reg .u64 a; cvta.to.global.u64 a, %1; atom.acq_rel.gpu.global.add.u32 %0, [a], %2; }"
                     : "=r"(old) : "l"(&d_count), "r"(1u) : "memory");
        if (old + 1u == r * NCTA) {
            asm volatile("{ .reg .u64 a; cvta.to.global.u64 a, %0; st.release.gpu.global.u32 [a], %1; }"
                         :: "l"(&d_release), "r"(r) : "memory");
        } else {
            unsigned v;
            do {
                asm volatile("{ .reg .u64 a; cvta.to.global.u64 a, %1; ld.acquire.gpu.global.u32 %0, [a]; }"
                             : "=r"(v) : "l"(&d_release) : "memory");
            } while (v < r);
        }
    }
    __syncthreads();
}

// bulk copy global(L2, .cg) -> shared, float4-wide, 256 threads
__device__ __forceinline__ void copy4(float* dst, const float* src, int nfl)
{
    const float4* s = (const float4*)src;
    float4* d = (float4*)dst;
    int n4 = nfl >> 2;
    for (int i = threadIdx.x; i < n4; i += 256) d[i] = __ldcg(s + i);
}

// gate accumulation: a01=(i,f), a23=(g,o); weights ulonglong2 (two f32x2), hv from smem
__device__ __forceinline__ void accseg(unsigned long long& a01, unsigned long long& a23,
                                       const ulonglong2* __restrict__ P,
                                       const float* __restrict__ vs, int K, int b)
{
#pragma unroll 8
    for (int k = 0; k < K; k++) {
        unsigned long long hh = pk2(vs[k*NB + b]);
        ulonglong2 w = __ldg(P + k);
        fma2(a01, w.x, hh);
        fma2(a23, w.y, hh);
    }
}

__device__ __forceinline__ void accx(unsigned long long& a01, unsigned long long& a23,
                                     const ulonglong2* __restrict__ P,
                                     float x0, float x1, float x2)
{
    ulonglong2 w0 = __ldg(P+0), w1 = __ldg(P+1), w2 = __ldg(P+2);
    unsigned long long X0 = pk2(x0), X1 = pk2(x1), X2 = pk2(x2);
    fma2(a01, w0.x, X0); fma2(a23, w0.y, X0);
    fma2(a01, w1.x, X1); fma2(a23, w1.y, X1);
    fma2(a01, w2.x, X2); fma2(a23, w2.y, X2);
}

__device__ __forceinline__ float lstm_tail(unsigned long long a01, unsigned long long a23,
                                           const float* __restrict__ p, int u,
                                           float* cArr, int o)
{
    float zi, zf, zg, zo;
    upk(a01, zi, zf); upk(a23, zg, zo);
    float c  = cArr[o];                 // CTA-private state: plain load ok
    float ig = sigf(zi + __ldg(p + u)        * c);
    float fg = sigf(zf + __ldg(p + NU + u)   * c);
    float cn = fg*c + ig*tanhf(zg);
    float og = sigf(zo + __ldg(p + 2*NU + u) * cn);
    cArr[o] = cn;
    return og * tanhf(cn);
}

// =====================================================================
// persistent RNN kernel
// =====================================================================
__global__ void __launch_bounds__(256, 1)
rnn_kernel(const float* __restrict__ strokes,
           const int*   __restrict__ chars,
           const int*   __restrict__ lens,
           const float* __restrict__ b0, const float* __restrict__ p0,
           const float* __restrict__ b1, const float* __restrict__ p1,
           const float* __restrict__ b2, const float* __restrict__ p2,
           const float* __restrict__ Watt, const float* __restrict__ batt,
           const float* __restrict__ Wmdn, const float* __restrict__ bmdn,
           float* __restrict__ out)
{
    extern __shared__ float smem[];
    float* s_h   = smem;            // 12800 floats: staged h-vector [k][b]
    float* s_wc  = smem + 12800;    // 2336  floats: staged w-vector [k][b]
    float* s_red = smem + 15136;    // 1024  floats: stage-4 partial reduction
    float* s_att = smem + 16160;    // 8*76: attention scatter scratch

    const int cta  = blockIdx.x;
    const int tid  = threadIdx.x;
    const int lane = tid & 31;
    const int wib  = tid >> 5;
    const int gw   = cta*8 + wib;
    const int b    = lane;
    unsigned rnd = 0;

    // ---- init ----
    {
        int g = cta*256 + tid, gs = NCTA*256;
        for (int i = g; i < NU*NB; i += gs) {
            __stcg(&d_h1a[i], 0.f); __stcg(&d_c1[i], 0.f);
            __stcg(&d_h2[i], 0.f);  __stcg(&d_c2[i], 0.f);
            __stcg(&d_h3[i], 0.f);  __stcg(&d_c3[i], 0.f);
        }
        for (int i = g; i < NC*NB; i += gs) __stcg(&d_wT[i], 0.f);
        for (int i = g; i < NB*NKG; i += gs) __stcg(&d_kappa[i], 0.f);
    }
    gsync(++rnd);

    for (int t = 0; t < NT; t++) {
        const float* h1prev = (t & 1) ? d_h1b : d_h1a;
        float*       h1cur  = (t & 1) ? d_h1a : d_h1b;

        const float* xp = strokes + (b*NT + t)*3;
        float x0 = __ldg(xp+0), x1 = __ldg(xp+1), x2 = __ldg(xp+2);

        // ============ stage 1: z1+LSTM1 | R2->Z2p | R3->R3p ============
        if (cta < 50) {
            copy4(s_h,  h1prev, NU*NB);
            copy4(s_wc, d_wT,   NC*NB);
            __syncthreads();
            int u = cta*8 + wib;
            unsigned long long a01 = pk(__ldg(b0+u),      __ldg(b0+NU+u));
            unsigned long long a23 = pk(__ldg(b0+2*NU+u), __ldg(b0+3*NU+u));
            const ulonglong2* P = (const ulonglong2*)(d_P0 + u*476);
            accx(a01, a23, P, x0, x1, x2);
            accseg(a01, a23, P+3,  s_wc, NC, b);
            accseg(a01, a23, P+76, s_h,  NU, b);
            int o = u*NB + b;
            __stcg(&h1cur[o], lstm_tail(a01, a23, p0, u, d_c1, o));
        } else if (cta < 100) {
            copy4(s_h, d_h2, NU*NB);
            __syncthreads();
            int u = (cta-50)*8 + wib;
            unsigned long long a01 = pk(__ldg(b1+u),      __ldg(b1+NU+u));
            unsigned long long a23 = pk(__ldg(b1+2*NU+u), __ldg(b1+3*NU+u));
            const ulonglong2* P = (const ulonglong2*)(d_P1r + u*403);
            accx(a01, a23, P, x0, x1, x2);
            accseg(a01, a23, P+3, s_h, NU, b);
            float g0,g1,g2,g3; upk(a01,g0,g1); upk(a23,g2,g3);
            float* dp = d_Z2p + u*128 + b;
            __stcg(dp+0,g0); __stcg(dp+32,g1); __stcg(dp+64,g2); __stcg(dp+96,g3);
        } else {
            copy4(s_h, d_h3, NU*NB);
            __syncthreads();
            int u = (cta-100)*8 + wib;
            unsigned long long a01 = pk(__ldg(b2+u),      __ldg(b2+NU+u));
            unsigned long long a23 = pk(__ldg(b2+2*NU+u), __ldg(b2+3*NU+u));
            const ulonglong2* P = (const ulonglong2*)(d_P2r + u*403);
            accx(a01, a23, P, x0, x1, x2);
            accseg(a01, a23, P+3, s_h, NU, b);
            float g0,g1,g2,g3; upk(a01,g0,g1); upk(a23,g2,g3);
            float* dp = d_R3p + u*128 + b;
            __stcg(dp+0,g0); __stcg(dp+32,g1); __stcg(dp+64,g2); __stcg(dp+96,g3);
        }
        gsync(++rnd);

        // ============ stage 2: Z2h halves (2 warps/unit) | attention ============
        if (cta < 100) {
            copy4(s_h, h1cur, NU*NB);
            __syncthreads();
            int u = cta*4 + (wib>>1);
            int half = wib & 1;
            unsigned long long a01 = 0ull, a23 = 0ull;
            const ulonglong2* P = (const ulonglong2*)(d_P1h + u*400);
            accseg(a01, a23, P + half*200, s_h + half*200*NB, 200, b);
            float g0,g1,g2,g3; upk(a01,g0,g1); upk(a23,g2,g3);
            float* dp = d_Z2h2 + half*(NU*4*NB) + u*128 + b;
            __stcg(dp+0,g0); __stcg(dp+32,g1); __stcg(dp+64,g2); __stcg(dp+96,g3);
        } else if (cta < 104) {
            copy4(s_h, h1cur, NU*NB);
            __syncthreads();
            int ab = (cta-100)*8 + wib;
            float att = 0.f;
            if (lane < 30) {
                float acc = __ldg(batt + lane);
#pragma unroll 8
                for (int k = 0; k < NU; k++)
                    acc = fmaf(s_h[k*NB + ab], __ldg(Watt + k*30 + lane), acc);
                att = acc;
            }
            const unsigned FULL = 0xffffffffu;
            float ah = __shfl_sync(FULL, att, (lane < 10) ? lane      : 0);
            float bh = __shfl_sync(FULL, att, (lane < 10) ? lane + 10 : 10);
            float kh = __shfl_sync(FULL, att, (lane < 10) ? lane + 20 : 20);
            float alpha = 0.f, beta = 0.f, kap = 0.f;
            if (lane < 10) {
                alpha = expf(ah);
                beta  = expf(bh);
                kap   = d_kappa[ab*NKG + lane] + expf(kh);  // private to this thread
                d_kappa[ab*NKG + lane] = kap;
            }
            float* sw = s_att + wib*76;
            for (int c = lane; c < NC; c += 32) sw[c] = 0.f;
            __syncwarp();
            int lb = __ldg(lens + ab);
#pragma unroll
            for (int half = 0; half < 2; half++) {
                int uu = lane + half*32;
                float phi = 0.f;
#pragma unroll
                for (int g = 0; g < NKG; g++) {
                    float ag = __shfl_sync(FULL, alpha, g);
                    float bg = __shfl_sync(FULL, beta,  g);
                    float kg = __shfl_sync(FULL, kap,   g);
                    float df = kg - (float)uu;
                    phi = fmaf(ag, expf(-bg*df*df), phi);
                }
                if (uu < NUC && uu < lb) {
                    int c = __ldg(chars + ab*NUC + uu);
                    atomicAdd(&sw[c], phi);
                }
            }
            __syncwarp();
            for (int c = lane; c < NC; c += 32) __stcg(&d_wT[c*NB + ab], sw[c]);
        }
        gsync(++rnd);

        // ============ stage 3: z2 = Z2p + Z2h(h0+h1) + w@P1w -> LSTM2 ============
        if (cta < 50) {
            copy4(s_wc, d_wT, NC*NB);
            __syncthreads();
            int u = cta*8 + wib;
            int o4 = u*128 + b;
            float z0 = __ldcg(d_Z2p+o4)    + __ldcg(d_Z2h2+o4)    + __ldcg(d_Z2h2+NU*4*NB+o4);
            float z1 = __ldcg(d_Z2p+o4+32) + __ldcg(d_Z2h2+o4+32) + __ldcg(d_Z2h2+NU*4*NB+o4+32);
            float z2 = __ldcg(d_Z2p+o4+64) + __ldcg(d_Z2h2+o4+64) + __ldcg(d_Z2h2+NU*4*NB+o4+64);
            float z3 = __ldcg(d_Z2p+o4+96) + __ldcg(d_Z2h2+o4+96) + __ldcg(d_Z2h2+NU*4*NB+o4+96);
            unsigned long long a01 = pk(z0,z1), a23 = pk(z2,z3);
            accseg(a01, a23, (const ulonglong2*)(d_P1w + u*73), s_wc, NC, b);
            int o = u*NB + b;
            __stcg(&d_h2[o], lstm_tail(a01, a23, p1, u, d_c2, o));
        }
        gsync(++rnd);

        // ============ stage 4: z3 = R3p + [w,h2]@P2wh (2 warps/unit) -> LSTM3 ============
        if (cta < 100) {
            copy4(s_wc, d_wT, NC*NB);
            copy4(s_h,  d_h2, NU*NB);
            __syncthreads();
            int u = cta*4 + (wib>>1);
            int half = wib & 1;
            unsigned long long a01 = 0ull, a23 = 0ull;
            const ulonglong2* P = (const ulonglong2*)(d_P2wh + u*473);
            if (half == 0) {
                accseg(a01, a23, P,    s_wc, NC, b);           // w part (73)
                accseg(a01, a23, P+73, s_h, 167, b);           // h2[0:167)
            } else {
                accseg(a01, a23, P+240, s_h + 167*NB, 233, b); // h2[167:400)
            }
            float g0,g1,g2,g3; upk(a01,g0,g1); upk(a23,g2,g3);
            float* rp = s_red + wib*128 + b;
            rp[0]=g0; rp[32]=g1; rp[64]=g2; rp[96]=g3;
            __syncthreads();
            if (wib < 4) {
                int uu = cta*4 + wib;
                int o4 = uu*128 + b;
                const float* r0 = s_red + (2*wib)*128 + b;
                const float* r1 = s_red + (2*wib+1)*128 + b;
                float z0 = __ldcg(d_R3p+o4)    + r0[0]  + r1[0];
                float z1 = __ldcg(d_R3p+o4+32) + r0[32] + r1[32];
                float z2 = __ldcg(d_R3p+o4+64) + r0[64] + r1[64];
                float z3 = __ldcg(d_R3p+o4+96) + r0[96] + r1[96];
                unsigned long long a01b = pk(z0,z1), a23b = pk(z2,z3);
                int o = uu*NB + b;
                float hv = lstm_tail(a01b, a23b, p2, uu, d_c3, o);
                __stcg(&d_h3[o], hv);
                __stcg(&d_h3all[(t*NU + uu)*NB + b], hv);
            }
        }
        gsync(++rnd);
    }

    // ================= MDN head =================
    for (int task = gw; task < NB*NT; task += NWARPS) {
        int bb = task / NT;
        int tt = task - bb*NT;
        const float* h3p = d_h3all + (tt*NU)*NB + bb;

        int j0 = lane, j1 = lane + 32, j2 = lane + 64, j3 = lane + 96;
        float a0 = __ldg(bmdn + j0);
        float a1 = __ldg(bmdn + j1);
        float a2 = __ldg(bmdn + j2);
        float a3 = (j3 < NO) ? __ldg(bmdn + j3) : 0.f;
#pragma unroll 4
        for (int k = 0; k < NU; k++) {
            float hv = __ldcg(h3p + k*NB);
            const float* wr = Wmdn + k*NO;
            a0 = fmaf(hv, __ldg(wr + j0), a0);
            a1 = fmaf(hv, __ldg(wr + j1), a1);
            a2 = fmaf(hv, __ldg(wr + j2), a2);
            a3 = fmaf(hv, (j3 < NO) ? __ldg(wr + j3) : 0.f, a3);
        }
        const unsigned FULL = 0xffffffffu;
        float v = (lane < 20) ? a0 : -INFINITY;
#pragma unroll
        for (int off = 16; off > 0; off >>= 1) v = fmaxf(v, __shfl_xor_sync(FULL, v, off));
        float e = (lane < 20) ? expf(a0 - v) : 0.f;
        float s = e;
#pragma unroll
        for (int off = 16; off > 0; off >>= 1) s += __shfl_xor_sync(FULL, s, off);

        float* op = out + (bb*NT + tt)*NO;
        op[j0] = (lane < 20) ? (e / s) : a0;       // pi | mu1
        op[j1] = (j1 >= 60) ? expf(a1) : a1;       // mu | s1(60-63)
        op[j2] = expf(a2);                         // s1/s2
        if (j3 < NO) {
            float o3;
            if (j3 < 100)      o3 = expf(a3);      // s2
            else if (j3 < 120) o3 = tanhf(a3);     // rho
            else               o3 = sigf(a3);      // eos
            op[j3] = o3;
        }
    }
}

// =====================================================================
// launch
// =====================================================================
extern "C" void kernel_launch(void* const* d_in, const int* in_sizes, int n_in,
                              void* d_out, int out_size)
{
    const float* strokes = (const float*)d_in[0];
    const int*   chars   = (const int*)  d_in[1];
    const int*   lens    = (const int*)  d_in[2];
    const float* Wx0 = (const float*)d_in[3];
    const float* Wh0 = (const float*)d_in[4];
    const float* b0  = (const float*)d_in[5];
    const float* p0  = (const float*)d_in[6];
    const float* Wx1 = (const float*)d_in[7];
    const float* Wh1 = (const float*)d_in[8];
    const float* b1  = (const float*)d_in[9];
    const float* p1  = (const float*)d_in[10];
    const float* Wx2 = (const float*)d_in[11];
    const float* Wh2 = (const float*)d_in[12];
    const float* b2  = (const float*)d_in[13];
    const float* p2  = (const float*)d_in[14];
    const float* Watt = (const float*)d_in[15];
    const float* batt = (const float*)d_in[16];
    const float* Wmdn = (const float*)d_in[17];
    const float* bmdn = (const float*)d_in[18];
    float* out = (float*)d_out;

    static int smem_set = 0;
    const int SMEM_BYTES = 16768 * 4;   // 67072
    if (!smem_set) {
        cudaFuncSetAttribute(rnn_kernel, cudaFuncAttributeMaxDynamicSharedMemorySize, SMEM_BYTES);
        smem_set = 1;
    }

    pack_kernel<<<256, 256>>>(Wx0, Wh0, Wx1, Wh1, Wx2, Wh2);
    rnn_kernel<<<NCTA, 256, SMEM_BYTES>>>(strokes, chars, lens,
                                          b0, p0, b1, p1, b2, p2,
                                          Watt, batt, Wmdn, bmdn, out);
}